// round 7
// baseline (speedup 1.0000x reference)
#include <cuda_runtime.h>
#include <cstdint>

// ---------------------------------------------------------------------------
// Problem constants
// ---------------------------------------------------------------------------
#define BATCH  256
#define SEQ    2048
#define IND    4
#define HID    256

// 8 clusters x 8 CTAs = 64 CTAs (single wave).
// Cluster owns MG=32 batch rows; CTA rank r owns h-indices [32r,32r+32)
// -> 128 W_hh rows (4 gates x 32) x 256 cols as tf32 register fragments.
// 8 warps: warp = (kg in {0,1}, nq in {0..3}).
// Exchange: h slices through per-cluster L2 buffer (STG -> release-arrive ->
// acquire-wait -> LDG.cg pull), NOT DSMEM fabric.
#define CLUSTER 8
#define NCLUST  8
#define MG      32
#define JPC     32
#define THREADS 256

#define AS_KSTR 40
#define AS_BUF  (HID * AS_KSTR)          // 10240 floats (single buffer now)
#define ZS_RSTR 132
#define ZS_BUF  (MG * ZS_RSTR)           // 4224 floats per k-group

// dynamic smem layout (float offsets)
#define OFF_AS    16
#define OFF_ZS    (OFF_AS + AS_BUF)          // 10256
#define OFF_WIH   (OFF_ZS + 2 * ZS_BUF)      // 18704
#define OFF_BIAS  (OFF_WIH + 512)            // 19216
#define OFF_XS    (OFF_BIAS + 128)           // 19344
#define SMEM_FLOATS (OFF_XS + 2 * MG * 4)    // 19600
#define SMEM_BYTES  (SMEM_FLOATS * 4)        // 78400

// ---------------------------------------------------------------------------
// Global scratch
// ---------------------------------------------------------------------------
__device__ float g_hx[NCLUST][2][HID * MG];  // per-cluster h exchange (A layout, stride 32)
__device__ float g_hfin[BATCH * HID];
__device__ float g_feat[2 * BATCH];

// ---------------------------------------------------------------------------
// helpers
// ---------------------------------------------------------------------------
__device__ __forceinline__ uint32_t tf32u(float v) {
    uint32_t r; asm("cvt.rna.tf32.f32 %0, %1;" : "=r"(r) : "f"(v)); return r;
}
__device__ __forceinline__ float rtf32(float v) { return __uint_as_float(tf32u(v)); }
__device__ __forceinline__ float tanh_a(float x) {
    float y; asm("tanh.approx.f32 %0, %1;" : "=f"(y) : "f"(x)); return y;
}
__device__ __forceinline__ float sig_t(float x) { return 0.5f * tanh_a(0.5f * x) + 0.5f; }
__device__ __forceinline__ float fast_sigmoid(float x) {
    float e = __expf(-x); return __fdividef(1.0f, 1.0f + e);
}
__device__ __forceinline__ float dot4(float4 a, float4 b) {
    return a.x * b.x + a.y * b.y + a.z * b.z + a.w * b.w;
}
__device__ __forceinline__ uint32_t smem_u32(const void* p) {
    uint32_t a;
    asm("{ .reg .u64 t; cvta.to.shared.u64 t, %1; cvt.u32.u64 %0, t; }" : "=r"(a) : "l"(p));
    return a;
}
__device__ __forceinline__ uint32_t cta_rank() {
    uint32_t r; asm("mov.u32 %0, %%cluster_ctarank;" : "=r"(r)); return r;
}
__device__ __forceinline__ uint32_t mapa_rank(uint32_t addr, uint32_t rank) {
    uint32_t r; asm("mapa.shared::cluster.u32 %0, %1, %2;" : "=r"(r) : "r"(addr), "r"(rank));
    return r;
}
__device__ __forceinline__ void mbar_init(uint32_t mbar, uint32_t cnt) {
    asm volatile("mbarrier.init.shared.b64 [%0], %1;" :: "r"(mbar), "r"(cnt) : "memory");
}
__device__ __forceinline__ void mbar_arrive_remote_rel(uint32_t mbar, uint32_t rank) {
    uint32_t r = mapa_rank(mbar, rank);
    asm volatile("mbarrier.arrive.release.cluster.shared::cluster.b64 _, [%0];"
                 :: "r"(r) : "memory");
}
// acquire at CLUSTER scope: makes peers' released gmem writes visible to our LDG
__device__ __forceinline__ void mbar_wait_acq_cluster(uint32_t mbar, uint32_t parity) {
    asm volatile(
        "{\n\t.reg .pred P;\n\t"
        "W_%=:\n\t"
        "mbarrier.try_wait.parity.acquire.cluster.shared::cta.b64 P, [%0], %1, 0x989680;\n\t"
        "@P bra D_%=;\n\t"
        "bra W_%=;\n\t"
        "D_%=:\n\t}"
        :: "r"(mbar), "r"(parity) : "memory");
}

// ---------------------------------------------------------------------------
// Kernel 1: conv_feat + kernel_sim
// ---------------------------------------------------------------------------
__global__ void feat_kernel(const float* __restrict__ x,
                            const float* __restrict__ conv_w,
                            const float* __restrict__ conv_b) {
    __shared__ float r0[256];
    __shared__ float r1[256];
    int b = blockIdx.x, tid = threadIdx.x;
    float4 cw = *(const float4*)conv_w;
    float cb = conv_b[0];
    const float4* xr = (const float4*)(x + (size_t)b * SEQ * IND);
    float ssig = 0.f, ssq = 0.f;
    for (int s = tid; s < SEQ; s += 256) {
        float4 v = xr[s];
        float d = v.x * cw.x + v.y * cw.y + v.z * cw.z + v.w * cw.w + cb;
        ssig += fast_sigmoid(d);
        ssq  += v.x * v.x + v.y * v.y + v.z * v.z + v.w * v.w;
    }
    r0[tid] = ssig; r1[tid] = ssq;
    __syncthreads();
    for (int o = 128; o > 0; o >>= 1) {
        if (tid < o) { r0[tid] += r0[tid + o]; r1[tid] += r1[tid + o]; }
        __syncthreads();
    }
    if (tid == 0) {
        g_feat[b]         = r0[0] * (1.0f / SEQ);
        g_feat[BATCH + b] = __expf(-r1[0]);
    }
}

// ---------------------------------------------------------------------------
// Kernel 2: LSTM recurrence; h exchange through L2 (pull model)
// ---------------------------------------------------------------------------
__global__ void __cluster_dims__(CLUSTER, 1, 1) __launch_bounds__(THREADS, 1)
lstm_kernel(const float* __restrict__ x,
            const float* __restrict__ W_ih,
            const float* __restrict__ W_hh,
            const float* __restrict__ b_ih,
            const float* __restrict__ b_hh) {
    extern __shared__ float sm[];
    float* As    = sm + OFF_AS;       // [k][il(row)] stride 40, single buffer
    float* Zs    = sm + OFF_ZS;       // [kg][row][n] stride 132
    float* WihS  = sm + OFF_WIH;
    float* BiasS = sm + OFF_BIAS;
    float* Xs    = sm + OFF_XS;

    const uint32_t sbase  = smem_u32(sm);
    const uint32_t mbrdy0 = sbase + 0, mbrdy1 = sbase + 8;

    const int tid   = threadIdx.x;
    const int cid   = blockIdx.x / CLUSTER;
    const uint32_t rank = cta_rank();
    const int bbase = cid * MG;
    const int j0    = (int)rank * JPC;
    const int warp  = tid >> 5, lane = tid & 31;
    const int kg    = warp >> 2, nq = warp & 3;
    const int g     = lane >> 2, tig = lane & 3;

    // ---- one-time: W_hh register fragments (tf32) ----
    uint32_t Breg[4][16][2];
    #pragma unroll
    for (int s = 0; s < 4; ++s) {
        const int nl   = nq * 32 + s * 8 + g;
        const int gate = nl >> 5, jj = nl & 31;
        const float* wrow = W_hh + (size_t)(gate * HID + j0 + jj) * HID + kg * 128;
        #pragma unroll
        for (int kt = 0; kt < 16; ++kt) {
            Breg[s][kt][0] = tf32u(wrow[kt * 8 + tig]);
            Breg[s][kt][1] = tf32u(wrow[kt * 8 + tig + 4]);
        }
    }
    if (tid < 128) {
        int gate = tid >> 5, jj = tid & 31;
        int grow = gate * HID + j0 + jj;
        BiasS[tid] = b_ih[grow] + b_hh[grow];
        WihS[tid * 4 + 0] = W_ih[grow * IND + 0];
        WihS[tid * 4 + 1] = W_ih[grow * IND + 1];
        WihS[tid * 4 + 2] = W_ih[grow * IND + 2];
        WihS[tid * 4 + 3] = W_ih[grow * IND + 3];
    }
    for (int i = tid; i < AS_BUF; i += THREADS) As[i] = 0.0f;   // h_0 = 0
    if (tid < MG)
        *(float4*)(Xs + tid * 4) = *(const float4*)(x + (size_t)(bbase + tid) * SEQ * IND);
    if (tid == 0) {
        mbar_init(mbrdy0, 8);
        mbar_init(mbrdy1, 8);
        asm volatile("fence.mbarrier_init.release.cluster;" ::: "memory");
    }
    __syncthreads();
    asm volatile("barrier.cluster.arrive.aligned;" ::: "memory");
    asm volatile("barrier.cluster.wait.aligned;"   ::: "memory");

    // gate-phase ownership: col jl = tid&31, qh = tid>>5 ->
    // interleave positions 4qh..4qh+3 == rows {rbq+2qq, rbq+2qq+8, rbq+2qq+1, rbq+2qq+9}
    const int jl  = tid & 31;
    const int qh  = tid >> 5;
    const int qq  = qh & 3;
    const int rbq = (qh & 4) ? 16 : 0;
    const int rows[4] = { rbq + 2*qq, rbq + 2*qq + 8, rbq + 2*qq + 1, rbq + 2*qq + 9 };
    float cst[4] = {0.f, 0.f, 0.f, 0.f};
    uint32_t pf[2] = {0, 0};

    for (int t = 0; t < SEQ; ++t) {
        const int p = t & 1;
        const uint32_t mbrdy_p = p ? mbrdy1 : mbrdy0;
        const uint32_t mbrdy_n = p ? mbrdy0 : mbrdy1;

        // prefetch x_{t+1}
        float4 xpre;
        const bool do_x = (tid < MG) && (t + 1 < SEQ);
        if (do_x)
            xpre = *(const float4*)(x + ((size_t)(bbase + tid) * SEQ + (t + 1)) * IND);

        // ---- pull h from L2 into As (t=0: As locally zeroed) ----
        if (t > 0) {
            mbar_wait_acq_cluster(mbrdy_p, pf[p]);
            pf[p] ^= 1;
            const float4* src = (const float4*)g_hx[cid][p];
            float4 v0 = __ldcg(src + 0 * 256 + tid);
            float4 v1 = __ldcg(src + 1 * 256 + tid);
            float4 v2 = __ldcg(src + 2 * 256 + tid);
            float4 v3 = __ldcg(src + 3 * 256 + tid);
            float4 v4 = __ldcg(src + 4 * 256 + tid);
            float4 v5 = __ldcg(src + 5 * 256 + tid);
            float4 v6 = __ldcg(src + 6 * 256 + tid);
            float4 v7 = __ldcg(src + 7 * 256 + tid);
            // idx4 = it*256+tid: k = idx4>>3, pos = 4*(idx4&7); gmem stride 32 -> smem 40
            #define A_STS(it, v) { int idx4 = (it) * 256 + tid; \
                *(float4*)(As + (idx4 >> 3) * AS_KSTR + 4 * (idx4 & 7)) = v; }
            A_STS(0, v0) A_STS(1, v1) A_STS(2, v2) A_STS(3, v3)
            A_STS(4, v4) A_STS(5, v5) A_STS(6, v6) A_STS(7, v7)
            #undef A_STS
        }
        __syncthreads();

        // ---- z_partial(kg) = h @ W^T for this warp's 32 n-rows ----
        const uint32_t* Au = (const uint32_t*)As;
        float acc[2][4][4];
        #pragma unroll
        for (int mt = 0; mt < 2; ++mt)
            #pragma unroll
            for (int s = 0; s < 4; ++s)
                #pragma unroll
                for (int q = 0; q < 4; ++q) acc[mt][s][q] = 0.0f;

        #pragma unroll
        for (int kt = 0; kt < 16; ++kt) {
            const int kb = kg * 128 + kt * 8 + tig;
            uint2 A0  = *(const uint2*)(Au + (size_t)kb * AS_KSTR + 2 * g);
            uint2 A0b = *(const uint2*)(Au + (size_t)(kb + 4) * AS_KSTR + 2 * g);
            uint2 A1  = *(const uint2*)(Au + (size_t)kb * AS_KSTR + 16 + 2 * g);
            uint2 A1b = *(const uint2*)(Au + (size_t)(kb + 4) * AS_KSTR + 16 + 2 * g);
            #pragma unroll
            for (int s = 0; s < 4; ++s) {
                asm("mma.sync.aligned.m16n8k8.row.col.f32.tf32.tf32.f32 "
                    "{%0,%1,%2,%3},{%4,%5,%6,%7},{%8,%9},{%0,%1,%2,%3};"
                    : "+f"(acc[0][s][0]), "+f"(acc[0][s][1]), "+f"(acc[0][s][2]), "+f"(acc[0][s][3])
                    : "r"(A0.x), "r"(A0.y), "r"(A0b.x), "r"(A0b.y),
                      "r"(Breg[s][kt][0]), "r"(Breg[s][kt][1]));
                asm("mma.sync.aligned.m16n8k8.row.col.f32.tf32.tf32.f32 "
                    "{%0,%1,%2,%3},{%4,%5,%6,%7},{%8,%9},{%0,%1,%2,%3};"
                    : "+f"(acc[1][s][0]), "+f"(acc[1][s][1]), "+f"(acc[1][s][2]), "+f"(acc[1][s][3])
                    : "r"(A1.x), "r"(A1.y), "r"(A1b.x), "r"(A1b.y),
                      "r"(Breg[s][kt][0]), "r"(Breg[s][kt][1]));
            }
        }
        {
            float* Zp = Zs + kg * ZS_BUF;
            #pragma unroll
            for (int mt = 0; mt < 2; ++mt)
                #pragma unroll
                for (int s = 0; s < 4; ++s) {
                    const int n0 = nq * 32 + s * 8;
                    const int r0 = mt * 16 + g;
                    *(float2*)(Zp + (size_t)r0 * ZS_RSTR + n0 + 2 * tig) =
                        make_float2(acc[mt][s][0], acc[mt][s][1]);
                    *(float2*)(Zp + (size_t)(r0 + 8) * ZS_RSTR + n0 + 2 * tig) =
                        make_float2(acc[mt][s][2], acc[mt][s][3]);
                }
        }
        __syncthreads();
        if (do_x) *(float4*)(Xs + (p ^ 1) * (MG * 4) + tid * 4) = xpre;

        // ---- gates ----
        float hv[4];
        {
            const float4 wiv = *(const float4*)(WihS + (jl)      * 4);
            const float4 wfv = *(const float4*)(WihS + (32 + jl) * 4);
            const float4 wgv = *(const float4*)(WihS + (64 + jl) * 4);
            const float4 wov = *(const float4*)(WihS + (96 + jl) * 4);
            const float bi = BiasS[jl], bf = BiasS[32 + jl];
            const float bg = BiasS[64 + jl], bo = BiasS[96 + jl];
            #pragma unroll
            for (int q = 0; q < 4; ++q) {
                const int r = rows[q];
                const float4 xv = *(const float4*)(Xs + p * (MG * 4) + r * 4);
                const float* z0 = Zs + (size_t)r * ZS_RSTR;
                const float* z1 = z0 + ZS_BUF;
                const float ai = z0[jl]      + z1[jl]      + bi + dot4(wiv, xv);
                const float af = z0[32 + jl] + z1[32 + jl] + bf + dot4(wfv, xv);
                const float ag = z0[64 + jl] + z1[64 + jl] + bg + dot4(wgv, xv);
                const float ao = z0[96 + jl] + z1[96 + jl] + bo + dot4(wov, xv);
                const float gi = sig_t(ai), gf = sig_t(af), go = sig_t(ao);
                const float gg = tanh_a(ag);
                const float cn = gf * cst[q] + gi * gg;
                cst[q] = cn;
                hv[q] = rtf32(go * tanh_a(cn));
            }
        }

        if (t + 1 < SEQ) {
            // publish h slice to L2 (A layout, gmem stride 32) and signal peers.
            // Safe to overwrite g_hx[cid][p^1]: every CTA's ready[p] arrival
            // (posted AFTER its step-(t-1) read of p^1) gated our step-t entry.
            *(float4*)(&g_hx[cid][p ^ 1][(size_t)(j0 + jl) * MG + 4 * qh]) =
                make_float4(hv[0], hv[1], hv[2], hv[3]);
            __syncthreads();
            if (tid == 0) {
                asm volatile("fence.acq_rel.cluster;" ::: "memory");
                #pragma unroll
                for (uint32_t rk = 0; rk < CLUSTER; ++rk)
                    mbar_arrive_remote_rel(p ? mbrdy0 : mbrdy1, rk);
            }
        } else {
            #pragma unroll
            for (int q = 0; q < 4; ++q)
                g_hfin[(size_t)(bbase + rows[q]) * HID + j0 + jl] = hv[q];
        }
    }

    asm volatile("barrier.cluster.arrive.aligned;" ::: "memory");
    asm volatile("barrier.cluster.wait.aligned;"   ::: "memory");
}

// ---------------------------------------------------------------------------
// Kernel 3: head
// ---------------------------------------------------------------------------
__global__ void head_kernel(const float* __restrict__ fc_w,
                            const float* __restrict__ fc_b,
                            const float* __restrict__ out_w,
                            const float* __restrict__ out_b,
                            float* __restrict__ out) {
    __shared__ float hsh[HID];
    __shared__ float r0[256];
    __shared__ float r1[256];
    int b = blockIdx.x, tid = threadIdx.x;
    hsh[tid] = g_hfin[b * HID + tid];
    __syncthreads();
    float cf = g_feat[b], ks = g_feat[BATCH + b];
    const float* wr = fc_w + (size_t)tid * (HID + 2);
    float acc = fc_b[tid] + wr[0] * cf + wr[HID + 1] * ks;
    #pragma unroll 8
    for (int k = 0; k < HID; ++k) acc += wr[1 + k] * hsh[k];
    float hid = fmaxf(acc, 0.0f);
    r0[tid] = hid * out_w[tid];
    r1[tid] = hid * out_w[HID + tid];
    __syncthreads();
    for (int o = 128; o > 0; o >>= 1) {
        if (tid < o) { r0[tid] += r0[tid + o]; r1[tid] += r1[tid + o]; }
        __syncthreads();
    }
    if (tid == 0) {
        float l0 = r0[0] + out_b[0];
        float l1 = r1[0] + out_b[1];
        float m  = fmaxf(l0, l1);
        float e0 = __expf(l0 - m), e1 = __expf(l1 - m);
        float inv = __fdividef(1.0f, e0 + e1);
        out[b * 2 + 0] = e0 * inv;
        out[b * 2 + 1] = e1 * inv;
    }
}

// ---------------------------------------------------------------------------
// launch (lstm first so the fixed ncu sampling slot captures it)
// ---------------------------------------------------------------------------
extern "C" void kernel_launch(void* const* d_in, const int* in_sizes, int n_in,
                              void* d_out, int out_size) {
    const float* x      = (const float*)d_in[0];
    const float* conv_w = (const float*)d_in[1];
    const float* conv_b = (const float*)d_in[2];
    const float* W_ih   = (const float*)d_in[3];
    const float* W_hh   = (const float*)d_in[4];
    const float* b_ih   = (const float*)d_in[5];
    const float* b_hh   = (const float*)d_in[6];
    const float* fc_w   = (const float*)d_in[7];
    const float* fc_b   = (const float*)d_in[8];
    const float* out_w  = (const float*)d_in[9];
    const float* out_b  = (const float*)d_in[10];
    float* out = (float*)d_out;

    cudaFuncSetAttribute(lstm_kernel, cudaFuncAttributeMaxDynamicSharedMemorySize,
                         SMEM_BYTES);

    lstm_kernel<<<NCLUST * CLUSTER, THREADS, SMEM_BYTES>>>(x, W_ih, W_hh, b_ih, b_hh);
    feat_kernel<<<BATCH, 256>>>(x, conv_w, conv_b);
    head_kernel<<<BATCH, 256>>>(fc_w, fc_b, out_w, out_b, out);
}

// round 8
// speedup vs baseline: 1.7923x; 1.7923x over previous
#include <cuda_runtime.h>
#include <cstdint>

// ---------------------------------------------------------------------------
// Problem constants
// ---------------------------------------------------------------------------
#define BATCH  256
#define SEQ    2048
#define IND    4
#define HID    256

// 8 clusters x 8 CTAs = 64 CTAs (single wave).
// Cluster owns MG=32 batch rows; CTA rank r owns h-indices [32r,32r+32)
// -> 128 W_hh rows (4 gates x 32) x 256 cols as tf32 register fragments.
// 8 warps: warp = (kg in {0,1}, nq in {0..3}).
// Exchange: STG slice -> L2, then ONE cp.async.bulk multicast::cluster per CTA
// delivers it into all 8 CTAs' As buffers (complete_tx at each full barrier).
#define CLUSTER 8
#define NCLUST  8
#define MG      32
#define JPC     32
#define THREADS 256

#define AS_KSTR 40
#define AS_BUF  (HID * AS_KSTR)          // 10240 floats per buffer
#define ZS_RSTR 132
#define ZS_BUF  (MG * ZS_RSTR)           // 4224 floats per k-group
#define SLICE_W (JPC * AS_KSTR)          // 1280 words per CTA slice
#define SLICE_B (SLICE_W * 4)            // 5120 bytes

// dynamic smem layout (float offsets)
#define OFF_AS    16
#define OFF_ZS    (OFF_AS + 2 * AS_BUF)      // 20496
#define OFF_WIH   (OFF_ZS + 2 * ZS_BUF)      // 28944
#define OFF_BIAS  (OFF_WIH + 512)            // 29456
#define OFF_XS    (OFF_BIAS + 128)           // 29584
#define SMEM_FLOATS (OFF_XS + 2 * MG * 4)    // 29840
#define SMEM_BYTES  (SMEM_FLOATS * 4)        // 119360

#define FULL_TX (8 * SLICE_B)             // 40960 bytes (8 multicast slices)

// ---------------------------------------------------------------------------
// Global scratch
// ---------------------------------------------------------------------------
__device__ float g_hx[NCLUST][2][CLUSTER * SLICE_W];  // L2 exchange staging
__device__ float g_hfin[BATCH * HID];
__device__ float g_feat[2 * BATCH];

// ---------------------------------------------------------------------------
// helpers
// ---------------------------------------------------------------------------
__device__ __forceinline__ uint32_t tf32u(float v) {
    uint32_t r; asm("cvt.rna.tf32.f32 %0, %1;" : "=r"(r) : "f"(v)); return r;
}
__device__ __forceinline__ float rtf32(float v) { return __uint_as_float(tf32u(v)); }
__device__ __forceinline__ float tanh_a(float x) {
    float y; asm("tanh.approx.f32 %0, %1;" : "=f"(y) : "f"(x)); return y;
}
__device__ __forceinline__ float sig_t(float x) { return 0.5f * tanh_a(0.5f * x) + 0.5f; }
__device__ __forceinline__ float fast_sigmoid(float x) {
    float e = __expf(-x); return __fdividef(1.0f, 1.0f + e);
}
__device__ __forceinline__ float dot4(float4 a, float4 b) {
    return a.x * b.x + a.y * b.y + a.z * b.z + a.w * b.w;
}
__device__ __forceinline__ uint32_t smem_u32(const void* p) {
    uint32_t a;
    asm("{ .reg .u64 t; cvta.to.shared.u64 t, %1; cvt.u32.u64 %0, t; }" : "=r"(a) : "l"(p));
    return a;
}
__device__ __forceinline__ uint32_t cta_rank() {
    uint32_t r; asm("mov.u32 %0, %%cluster_ctarank;" : "=r"(r)); return r;
}
__device__ __forceinline__ uint32_t mapa_rank(uint32_t addr, uint32_t rank) {
    uint32_t r; asm("mapa.shared::cluster.u32 %0, %1, %2;" : "=r"(r) : "r"(addr), "r"(rank));
    return r;
}
__device__ __forceinline__ void mbar_init(uint32_t mbar, uint32_t cnt) {
    asm volatile("mbarrier.init.shared.b64 [%0], %1;" :: "r"(mbar), "r"(cnt) : "memory");
}
__device__ __forceinline__ void mbar_expect(uint32_t mbar, uint32_t bytes) {
    asm volatile("mbarrier.arrive.expect_tx.shared.b64 _, [%0], %1;"
                 :: "r"(mbar), "r"(bytes) : "memory");
}
__device__ __forceinline__ void mbar_arrive_remote(uint32_t mbar, uint32_t rank) {
    uint32_t r = mapa_rank(mbar, rank);
    asm volatile("mbarrier.arrive.shared::cluster.b64 _, [%0];" :: "r"(r) : "memory");
}
__device__ __forceinline__ void mbar_wait(uint32_t mbar, uint32_t parity) {
    asm volatile(
        "{\n\t.reg .pred P;\n\t"
        "W_%=:\n\t"
        "mbarrier.try_wait.parity.acquire.cta.shared::cta.b64 P, [%0], %1, 0x989680;\n\t"
        "@P bra D_%=;\n\t"
        "bra W_%=;\n\t"
        "D_%=:\n\t}"
        :: "r"(mbar), "r"(parity) : "memory");
}
// one bulk, delivered to every CTA in ctaMask at the same local dst offset
__device__ __forceinline__ void bulk_mc_g2s(uint32_t dst, const void* src,
                                            uint32_t bytes, uint32_t mbar,
                                            uint16_t mask) {
    asm volatile("cp.async.bulk.shared::cluster.global."
                 "mbarrier::complete_tx::bytes.multicast::cluster "
                 "[%0], [%1], %2, [%3], %4;"
                 :: "r"(dst), "l"(src), "r"(bytes), "r"(mbar), "h"(mask) : "memory");
}

// ---------------------------------------------------------------------------
// Kernel 1: conv_feat + kernel_sim
// ---------------------------------------------------------------------------
__global__ void feat_kernel(const float* __restrict__ x,
                            const float* __restrict__ conv_w,
                            const float* __restrict__ conv_b) {
    __shared__ float r0[256];
    __shared__ float r1[256];
    int b = blockIdx.x, tid = threadIdx.x;
    float4 cw = *(const float4*)conv_w;
    float cb = conv_b[0];
    const float4* xr = (const float4*)(x + (size_t)b * SEQ * IND);
    float ssig = 0.f, ssq = 0.f;
    for (int s = tid; s < SEQ; s += 256) {
        float4 v = xr[s];
        float d = v.x * cw.x + v.y * cw.y + v.z * cw.z + v.w * cw.w + cb;
        ssig += fast_sigmoid(d);
        ssq  += v.x * v.x + v.y * v.y + v.z * v.z + v.w * v.w;
    }
    r0[tid] = ssig; r1[tid] = ssq;
    __syncthreads();
    for (int o = 128; o > 0; o >>= 1) {
        if (tid < o) { r0[tid] += r0[tid + o]; r1[tid] += r1[tid + o]; }
        __syncthreads();
    }
    if (tid == 0) {
        g_feat[b]         = r0[0] * (1.0f / SEQ);
        g_feat[BATCH + b] = __expf(-r1[0]);
    }
}

// ---------------------------------------------------------------------------
// Kernel 2: LSTM recurrence; exchange via L2 + bulk multicast (1 issue/CTA)
// ---------------------------------------------------------------------------
__global__ void __cluster_dims__(CLUSTER, 1, 1) __launch_bounds__(THREADS, 1)
lstm_kernel(const float* __restrict__ x,
            const float* __restrict__ W_ih,
            const float* __restrict__ W_hh,
            const float* __restrict__ b_ih,
            const float* __restrict__ b_hh) {
    extern __shared__ float sm[];
    float* As    = sm + OFF_AS;
    float* Zs    = sm + OFF_ZS;
    float* WihS  = sm + OFF_WIH;
    float* BiasS = sm + OFF_BIAS;
    float* Xs    = sm + OFF_XS;

    const uint32_t sbase   = smem_u32(sm);
    const uint32_t mbfull0 = sbase + 0,  mbfull1 = sbase + 8;
    const uint32_t mbdone0 = sbase + 16, mbdone1 = sbase + 24;

    const int tid   = threadIdx.x;
    const int cid   = blockIdx.x / CLUSTER;
    const uint32_t rank = cta_rank();
    const int bbase = cid * MG;
    const int j0    = (int)rank * JPC;
    const int warp  = tid >> 5, lane = tid & 31;
    const int kg    = warp >> 2, nq = warp & 3;
    const int g     = lane >> 2, tig = lane & 3;

    // ---- one-time: W_hh register fragments (tf32) ----
    uint32_t Breg[4][16][2];
    #pragma unroll
    for (int s = 0; s < 4; ++s) {
        const int nl   = nq * 32 + s * 8 + g;
        const int gate = nl >> 5, jj = nl & 31;
        const float* wrow = W_hh + (size_t)(gate * HID + j0 + jj) * HID + kg * 128;
        #pragma unroll
        for (int kt = 0; kt < 16; ++kt) {
            Breg[s][kt][0] = tf32u(wrow[kt * 8 + tig]);
            Breg[s][kt][1] = tf32u(wrow[kt * 8 + tig + 4]);
        }
    }
    if (tid < 128) {
        int gate = tid >> 5, jj = tid & 31;
        int grow = gate * HID + j0 + jj;
        BiasS[tid] = b_ih[grow] + b_hh[grow];
        WihS[tid * 4 + 0] = W_ih[grow * IND + 0];
        WihS[tid * 4 + 1] = W_ih[grow * IND + 1];
        WihS[tid * 4 + 2] = W_ih[grow * IND + 2];
        WihS[tid * 4 + 3] = W_ih[grow * IND + 3];
    }
    for (int i = tid; i < AS_BUF; i += THREADS) As[i] = 0.0f;   // h_0 = 0 (buf 0)
    if (tid < MG)
        *(float4*)(Xs + tid * 4) = *(const float4*)(x + (size_t)(bbase + tid) * SEQ * IND);
    if (tid == 0) {
        mbar_init(mbfull0, 1); mbar_init(mbfull1, 1);
        mbar_init(mbdone0, 8); mbar_init(mbdone1, 8);
        asm volatile("fence.mbarrier_init.release.cluster;" ::: "memory");
        mbar_expect(mbfull0, FULL_TX);
        mbar_expect(mbfull1, FULL_TX);
    }
    __syncthreads();
    asm volatile("barrier.cluster.arrive.aligned;" ::: "memory");
    asm volatile("barrier.cluster.wait.aligned;"   ::: "memory");

    // gate-phase ownership: col jl = tid&31, qh = tid>>5 ->
    // interleave positions 4qh..4qh+3 == rows {rbq+2qq, rbq+2qq+8, rbq+2qq+1, rbq+2qq+9}
    const int jl  = tid & 31;
    const int qh  = tid >> 5;
    const int qq  = qh & 3;
    const int rbq = (qh & 4) ? 16 : 0;
    const int rows[4] = { rbq + 2*qq, rbq + 2*qq + 8, rbq + 2*qq + 1, rbq + 2*qq + 9 };
    float cst[4] = {0.f, 0.f, 0.f, 0.f};
    uint32_t pf[2] = {0, 0}, pd[2] = {0, 0};

    for (int t = 0; t < SEQ; ++t) {
        const int p = t & 1;
        const uint32_t mbfull_p = p ? mbfull1 : mbfull0;
        const uint32_t mbfull_n = p ? mbfull0 : mbfull1;   // target of this step's push
        const uint32_t mbdone_p = p ? mbdone1 : mbdone0;
        const uint32_t mbdone_n = p ? mbdone0 : mbdone1;

        // prefetch x_{t+1}
        float4 xpre;
        const bool do_x = (tid < MG) && (t + 1 < SEQ);
        if (do_x)
            xpre = *(const float4*)(x + ((size_t)(bbase + tid) * SEQ + (t + 1)) * IND);

        // wait for A buffer p (step 0: locally zeroed)
        if (t > 0) {
            mbar_wait(mbfull_p, pf[p]);
            pf[p] ^= 1;
            if (tid == 0) mbar_expect(mbfull_p, FULL_TX);
        }

        // ---- z_partial(kg) = h @ W^T for this warp's 32 n-rows ----
        const uint32_t* Au = (const uint32_t*)(As + p * AS_BUF);
        float acc[2][4][4];
        #pragma unroll
        for (int mt = 0; mt < 2; ++mt)
            #pragma unroll
            for (int s = 0; s < 4; ++s)
                #pragma unroll
                for (int q = 0; q < 4; ++q) acc[mt][s][q] = 0.0f;

        #pragma unroll
        for (int kt = 0; kt < 16; ++kt) {
            const int kb = kg * 128 + kt * 8 + tig;
            uint2 A0  = *(const uint2*)(Au + (size_t)kb * AS_KSTR + 2 * g);
            uint2 A0b = *(const uint2*)(Au + (size_t)(kb + 4) * AS_KSTR + 2 * g);
            uint2 A1  = *(const uint2*)(Au + (size_t)kb * AS_KSTR + 16 + 2 * g);
            uint2 A1b = *(const uint2*)(Au + (size_t)(kb + 4) * AS_KSTR + 16 + 2 * g);
            #pragma unroll
            for (int s = 0; s < 4; ++s) {
                asm("mma.sync.aligned.m16n8k8.row.col.f32.tf32.tf32.f32 "
                    "{%0,%1,%2,%3},{%4,%5,%6,%7},{%8,%9},{%0,%1,%2,%3};"
                    : "+f"(acc[0][s][0]), "+f"(acc[0][s][1]), "+f"(acc[0][s][2]), "+f"(acc[0][s][3])
                    : "r"(A0.x), "r"(A0.y), "r"(A0b.x), "r"(A0b.y),
                      "r"(Breg[s][kt][0]), "r"(Breg[s][kt][1]));
                asm("mma.sync.aligned.m16n8k8.row.col.f32.tf32.tf32.f32 "
                    "{%0,%1,%2,%3},{%4,%5,%6,%7},{%8,%9},{%0,%1,%2,%3};"
                    : "+f"(acc[1][s][0]), "+f"(acc[1][s][1]), "+f"(acc[1][s][2]), "+f"(acc[1][s][3])
                    : "r"(A1.x), "r"(A1.y), "r"(A1b.x), "r"(A1b.y),
                      "r"(Breg[s][kt][0]), "r"(Breg[s][kt][1]));
            }
        }
        {
            float* Zp = Zs + kg * ZS_BUF;
            #pragma unroll
            for (int mt = 0; mt < 2; ++mt)
                #pragma unroll
                for (int s = 0; s < 4; ++s) {
                    const int n0 = nq * 32 + s * 8;
                    const int r0 = mt * 16 + g;
                    *(float2*)(Zp + (size_t)r0 * ZS_RSTR + n0 + 2 * tig) =
                        make_float2(acc[mt][s][0], acc[mt][s][1]);
                    *(float2*)(Zp + (size_t)(r0 + 8) * ZS_RSTR + n0 + 2 * tig) =
                        make_float2(acc[mt][s][2], acc[mt][s][3]);
                }
        }
        __syncthreads();

        // signal "A buffer p consumed" to all cluster CTAs
        if (tid == 0) {
            #pragma unroll
            for (uint32_t rk = 0; rk < CLUSTER; ++rk) mbar_arrive_remote(mbdone_p, rk);
        }
        if (do_x) *(float4*)(Xs + (p ^ 1) * (MG * 4) + tid * 4) = xpre;

        // ---- gates ----
        float hv[4];
        {
            const float4 wiv = *(const float4*)(WihS + (jl)      * 4);
            const float4 wfv = *(const float4*)(WihS + (32 + jl) * 4);
            const float4 wgv = *(const float4*)(WihS + (64 + jl) * 4);
            const float4 wov = *(const float4*)(WihS + (96 + jl) * 4);
            const float bi = BiasS[jl], bf = BiasS[32 + jl];
            const float bg = BiasS[64 + jl], bo = BiasS[96 + jl];
            #pragma unroll
            for (int q = 0; q < 4; ++q) {
                const int r = rows[q];
                const float4 xv = *(const float4*)(Xs + p * (MG * 4) + r * 4);
                const float* z0 = Zs + (size_t)r * ZS_RSTR;
                const float* z1 = z0 + ZS_BUF;
                const float ai = z0[jl]      + z1[jl]      + bi + dot4(wiv, xv);
                const float af = z0[32 + jl] + z1[32 + jl] + bf + dot4(wfv, xv);
                const float ag = z0[64 + jl] + z1[64 + jl] + bg + dot4(wgv, xv);
                const float ao = z0[96 + jl] + z1[96 + jl] + bo + dot4(wov, xv);
                const float gi = sig_t(ai), gf = sig_t(af), go = sig_t(ao);
                const float gg = tanh_a(ag);
                const float cn = gf * cst[q] + gi * gg;
                cst[q] = cn;
                hv[q] = rtf32(go * tanh_a(cn));
            }
        }
        // publish own slice to L2 staging (A layout, padded stride 40)
        {
            float* dst = &g_hx[cid][p ^ 1][(size_t)rank * SLICE_W + jl * AS_KSTR + 4 * qh];
            __stcg((float4*)dst, make_float4(hv[0], hv[1], hv[2], hv[3]));
        }
        __syncthreads();   // all slice STGs issued (cta-ordered before elected fence)

        // elected: wait peers consumed As[p^1], then ONE multicast bulk to all 8
        if (tid == 0) {
            if (t > 0) { mbar_wait(mbdone_n, pd[p ^ 1]); pd[p ^ 1] ^= 1; }
            asm volatile("fence.proxy.async.global;" ::: "memory");
            const uint32_t dstl = sbase + (OFF_AS + (p ^ 1) * AS_BUF + j0 * AS_KSTR) * 4;
            bulk_mc_g2s(dstl, &g_hx[cid][p ^ 1][(size_t)rank * SLICE_W],
                        SLICE_B, mbfull_n, (uint16_t)0xFF);
        }

        if (t == SEQ - 1) {
            #pragma unroll
            for (int q = 0; q < 4; ++q)
                g_hfin[(size_t)(bbase + rows[q]) * HID + j0 + jl] = hv[q];
        }
    }

    // drain final incoming multicasts (t=2047 targeted full[0]) before exit
    mbar_wait(mbfull0, pf[0]);
    asm volatile("barrier.cluster.arrive.aligned;" ::: "memory");
    asm volatile("barrier.cluster.wait.aligned;"   ::: "memory");
}

// ---------------------------------------------------------------------------
// Kernel 3: head
// ---------------------------------------------------------------------------
__global__ void head_kernel(const float* __restrict__ fc_w,
                            const float* __restrict__ fc_b,
                            const float* __restrict__ out_w,
                            const float* __restrict__ out_b,
                            float* __restrict__ out) {
    __shared__ float hsh[HID];
    __shared__ float r0[256];
    __shared__ float r1[256];
    int b = blockIdx.x, tid = threadIdx.x;
    hsh[tid] = g_hfin[b * HID + tid];
    __syncthreads();
    float cf = g_feat[b], ks = g_feat[BATCH + b];
    const float* wr = fc_w + (size_t)tid * (HID + 2);
    float acc = fc_b[tid] + wr[0] * cf + wr[HID + 1] * ks;
    #pragma unroll 8
    for (int k = 0; k < HID; ++k) acc += wr[1 + k] * hsh[k];
    float hid = fmaxf(acc, 0.0f);
    r0[tid] = hid * out_w[tid];
    r1[tid] = hid * out_w[HID + tid];
    __syncthreads();
    for (int o = 128; o > 0; o >>= 1) {
        if (tid < o) { r0[tid] += r0[tid + o]; r1[tid] += r1[tid + o]; }
        __syncthreads();
    }
    if (tid == 0) {
        float l0 = r0[0] + out_b[0];
        float l1 = r1[0] + out_b[1];
        float m  = fmaxf(l0, l1);
        float e0 = __expf(l0 - m), e1 = __expf(l1 - m);
        float inv = __fdividef(1.0f, e0 + e1);
        out[b * 2 + 0] = e0 * inv;
        out[b * 2 + 1] = e1 * inv;
    }
}

// ---------------------------------------------------------------------------
// launch (lstm first so the fixed ncu sampling slot captures it)
// ---------------------------------------------------------------------------
extern "C" void kernel_launch(void* const* d_in, const int* in_sizes, int n_in,
                              void* d_out, int out_size) {
    const float* x      = (const float*)d_in[0];
    const float* conv_w = (const float*)d_in[1];
    const float* conv_b = (const float*)d_in[2];
    const float* W_ih   = (const float*)d_in[3];
    const float* W_hh   = (const float*)d_in[4];
    const float* b_ih   = (const float*)d_in[5];
    const float* b_hh   = (const float*)d_in[6];
    const float* fc_w   = (const float*)d_in[7];
    const float* fc_b   = (const float*)d_in[8];
    const float* out_w  = (const float*)d_in[9];
    const float* out_b  = (const float*)d_in[10];
    float* out = (float*)d_out;

    cudaFuncSetAttribute(lstm_kernel, cudaFuncAttributeMaxDynamicSharedMemorySize,
                         SMEM_BYTES);

    lstm_kernel<<<NCLUST * CLUSTER, THREADS, SMEM_BYTES>>>(x, W_ih, W_hh, b_ih, b_hh);
    feat_kernel<<<BATCH, 256>>>(x, conv_w, conv_b);
    head_kernel<<<BATCH, 256>>>(fc_w, fc_b, out_w, out_b, out);
}

// round 9
// speedup vs baseline: 2.0534x; 1.1457x over previous
#include <cuda_runtime.h>
#include <cstdint>

// ---------------------------------------------------------------------------
// Problem constants
// ---------------------------------------------------------------------------
#define BATCH  256
#define SEQ    2048
#define IND    4
#define HID    256

// 8 clusters x 8 CTAs = 64 CTAs (single wave).
// Cluster owns 32 batch rows, split into TWO independent pipelined groups of
// 16 rows. CTA rank r owns h-indices [32r,32r+32) -> 128 W_hh rows as tf32
// register fragments. 8 warps: warp = (kg in {0,1}, nq in {0..3}).
// Per group: STG slice -> L2, ONE cp.async.bulk multicast::cluster delivers it
// into all 8 CTAs' A buffers; group B's compute hides group A's exchange.
#define CLUSTER 8
#define NCLUST  8
#define MG      32
#define MGG     16      // rows per pipeline group
#define JPC     32
#define THREADS 256

#define AS_KSTR 20                      // 16 rows + 4 pad words
#define AS_BUF  (HID * AS_KSTR)         // 5120 floats per buffer
#define ZS_RSTR 132
#define ZS_BUF  (MGG * ZS_RSTR)         // 2112 floats per k-group
#define SLICE_W (JPC * AS_KSTR)         // 640 words per CTA slice
#define SLICE_B (SLICE_W * 4)           // 2560 bytes
#define FULL_TX (8 * SLICE_B)           // 20480 bytes (8 multicast slices)

// dynamic smem layout (float offsets)
// mbarriers: full[g][p] at (g*2+p)*8 bytes, done[g][p] at 32+(g*2+p)*8 bytes
#define OFF_AS    16
#define OFF_ZS    (OFF_AS + 4 * AS_BUF)      // 20496  (A[g][p] = (g*2+p)*AS_BUF)
#define OFF_WIH   (OFF_ZS + 2 * ZS_BUF)      // 24720
#define OFF_BIAS  (OFF_WIH + 512)            // 25232
#define OFF_XS    (OFF_BIAS + 128)           // 25360
#define SMEM_FLOATS (OFF_XS + 2 * MG * 4)    // 25616
#define SMEM_BYTES  (SMEM_FLOATS * 4)        // 102464

// ---------------------------------------------------------------------------
// Global scratch
// ---------------------------------------------------------------------------
__device__ float g_hx[NCLUST][2][2][CLUSTER * SLICE_W];  // [clust][group][phase]
__device__ float g_hfin[BATCH * HID];
__device__ float g_feat[2 * BATCH];

// ---------------------------------------------------------------------------
// helpers
// ---------------------------------------------------------------------------
__device__ __forceinline__ uint32_t tf32u(float v) {
    uint32_t r; asm("cvt.rna.tf32.f32 %0, %1;" : "=r"(r) : "f"(v)); return r;
}
__device__ __forceinline__ float rtf32(float v) { return __uint_as_float(tf32u(v)); }
__device__ __forceinline__ float tanh_a(float x) {
    float y; asm("tanh.approx.f32 %0, %1;" : "=f"(y) : "f"(x)); return y;
}
__device__ __forceinline__ float sig_t(float x) { return 0.5f * tanh_a(0.5f * x) + 0.5f; }
__device__ __forceinline__ float fast_sigmoid(float x) {
    float e = __expf(-x); return __fdividef(1.0f, 1.0f + e);
}
__device__ __forceinline__ float dot4(float4 a, float4 b) {
    return a.x * b.x + a.y * b.y + a.z * b.z + a.w * b.w;
}
__device__ __forceinline__ uint32_t smem_u32(const void* p) {
    uint32_t a;
    asm("{ .reg .u64 t; cvta.to.shared.u64 t, %1; cvt.u32.u64 %0, t; }" : "=r"(a) : "l"(p));
    return a;
}
__device__ __forceinline__ uint32_t cta_rank() {
    uint32_t r; asm("mov.u32 %0, %%cluster_ctarank;" : "=r"(r)); return r;
}
__device__ __forceinline__ uint32_t mapa_rank(uint32_t addr, uint32_t rank) {
    uint32_t r; asm("mapa.shared::cluster.u32 %0, %1, %2;" : "=r"(r) : "r"(addr), "r"(rank));
    return r;
}
__device__ __forceinline__ void mbar_init(uint32_t mbar, uint32_t cnt) {
    asm volatile("mbarrier.init.shared.b64 [%0], %1;" :: "r"(mbar), "r"(cnt) : "memory");
}
__device__ __forceinline__ void mbar_expect(uint32_t mbar, uint32_t bytes) {
    asm volatile("mbarrier.arrive.expect_tx.shared.b64 _, [%0], %1;"
                 :: "r"(mbar), "r"(bytes) : "memory");
}
__device__ __forceinline__ void mbar_arrive_remote(uint32_t mbar, uint32_t rank) {
    uint32_t r = mapa_rank(mbar, rank);
    asm volatile("mbarrier.arrive.shared::cluster.b64 _, [%0];" :: "r"(r) : "memory");
}
__device__ __forceinline__ void mbar_wait(uint32_t mbar, uint32_t parity) {
    asm volatile(
        "{\n\t.reg .pred P;\n\t"
        "W_%=:\n\t"
        "mbarrier.try_wait.parity.acquire.cta.shared::cta.b64 P, [%0], %1, 0x989680;\n\t"
        "@P bra D_%=;\n\t"
        "bra W_%=;\n\t"
        "D_%=:\n\t}"
        :: "r"(mbar), "r"(parity) : "memory");
}
// one bulk, delivered to every CTA in ctaMask at the same local dst offset
__device__ __forceinline__ void bulk_mc_g2s(uint32_t dst, const void* src,
                                            uint32_t bytes, uint32_t mbar,
                                            uint16_t mask) {
    asm volatile("cp.async.bulk.shared::cluster.global."
                 "mbarrier::complete_tx::bytes.multicast::cluster "
                 "[%0], [%1], %2, [%3], %4;"
                 :: "r"(dst), "l"(src), "r"(bytes), "r"(mbar), "h"(mask) : "memory");
}

// ---------------------------------------------------------------------------
// Kernel 1: conv_feat + kernel_sim
// ---------------------------------------------------------------------------
__global__ void feat_kernel(const float* __restrict__ x,
                            const float* __restrict__ conv_w,
                            const float* __restrict__ conv_b) {
    __shared__ float r0[256];
    __shared__ float r1[256];
    int b = blockIdx.x, tid = threadIdx.x;
    float4 cw = *(const float4*)conv_w;
    float cb = conv_b[0];
    const float4* xr = (const float4*)(x + (size_t)b * SEQ * IND);
    float ssig = 0.f, ssq = 0.f;
    for (int s = tid; s < SEQ; s += 256) {
        float4 v = xr[s];
        float d = v.x * cw.x + v.y * cw.y + v.z * cw.z + v.w * cw.w + cb;
        ssig += fast_sigmoid(d);
        ssq  += v.x * v.x + v.y * v.y + v.z * v.z + v.w * v.w;
    }
    r0[tid] = ssig; r1[tid] = ssq;
    __syncthreads();
    for (int o = 128; o > 0; o >>= 1) {
        if (tid < o) { r0[tid] += r0[tid + o]; r1[tid] += r1[tid + o]; }
        __syncthreads();
    }
    if (tid == 0) {
        g_feat[b]         = r0[0] * (1.0f / SEQ);
        g_feat[BATCH + b] = __expf(-r1[0]);
    }
}

// ---------------------------------------------------------------------------
// Kernel 2: LSTM recurrence; two pipelined 16-row groups per cluster
// ---------------------------------------------------------------------------
__global__ void __cluster_dims__(CLUSTER, 1, 1) __launch_bounds__(THREADS, 1)
lstm_kernel(const float* __restrict__ x,
            const float* __restrict__ W_ih,
            const float* __restrict__ W_hh,
            const float* __restrict__ b_ih,
            const float* __restrict__ b_hh) {
    extern __shared__ float sm[];
    float* As    = sm + OFF_AS;
    float* Zs    = sm + OFF_ZS;
    float* WihS  = sm + OFF_WIH;
    float* BiasS = sm + OFF_BIAS;
    float* Xs    = sm + OFF_XS;

    const uint32_t sbase = smem_u32(sm);

    const int tid   = threadIdx.x;
    const int cid   = blockIdx.x / CLUSTER;
    const uint32_t rank = cta_rank();
    const int bbase = cid * MG;
    const int j0    = (int)rank * JPC;
    const int warp  = tid >> 5, lane = tid & 31;
    const int kg    = warp >> 2, nq = warp & 3;
    const int g     = lane >> 2, tig = lane & 3;

    // ---- one-time: W_hh register fragments (tf32) ----
    uint32_t Breg[4][16][2];
    #pragma unroll
    for (int s = 0; s < 4; ++s) {
        const int nl   = nq * 32 + s * 8 + g;
        const int gate = nl >> 5, jj = nl & 31;
        const float* wrow = W_hh + (size_t)(gate * HID + j0 + jj) * HID + kg * 128;
        #pragma unroll
        for (int kt = 0; kt < 16; ++kt) {
            Breg[s][kt][0] = tf32u(wrow[kt * 8 + tig]);
            Breg[s][kt][1] = tf32u(wrow[kt * 8 + tig + 4]);
        }
    }
    if (tid < 128) {
        int gate = tid >> 5, jj = tid & 31;
        int grow = gate * HID + j0 + jj;
        BiasS[tid] = b_ih[grow] + b_hh[grow];
        WihS[tid * 4 + 0] = W_ih[grow * IND + 0];
        WihS[tid * 4 + 1] = W_ih[grow * IND + 1];
        WihS[tid * 4 + 2] = W_ih[grow * IND + 2];
        WihS[tid * 4 + 3] = W_ih[grow * IND + 3];
    }
    // zero phase-0 A buffers of both groups (h_0 = 0)
    for (int i = tid; i < AS_BUF; i += THREADS) {
        As[i] = 0.0f;                 // group 0, phase 0
        As[2 * AS_BUF + i] = 0.0f;    // group 1, phase 0
    }
    if (tid < MG)
        *(float4*)(Xs + tid * 4) = *(const float4*)(x + (size_t)(bbase + tid) * SEQ * IND);
    if (tid == 0) {
        #pragma unroll
        for (int i = 0; i < 4; ++i) {
            mbar_init(sbase + i * 8, 1);        // full[g][p]
            mbar_init(sbase + 32 + i * 8, 8);   // done[g][p]
        }
        asm volatile("fence.mbarrier_init.release.cluster;" ::: "memory");
        #pragma unroll
        for (int i = 0; i < 4; ++i) mbar_expect(sbase + i * 8, FULL_TX);
    }
    __syncthreads();
    asm volatile("barrier.cluster.arrive.aligned;" ::: "memory");
    asm volatile("barrier.cluster.wait.aligned;"   ::: "memory");

    // gate-phase ownership: col jl = tid&31; thread qh = tid>>5 owns group rows
    // {qh, qh+8}  (interleave positions 2qh, 2qh+1)
    const int jl = tid & 31;
    const int qh = tid >> 5;

    // hoisted loop-invariant gate weights/biases
    const float4 wiv = *(const float4*)(WihS + (jl)      * 4);
    const float4 wfv = *(const float4*)(WihS + (32 + jl) * 4);
    const float4 wgv = *(const float4*)(WihS + (64 + jl) * 4);
    const float4 wov = *(const float4*)(WihS + (96 + jl) * 4);
    const float bi = BiasS[jl], bf = BiasS[32 + jl];
    const float bg = BiasS[64 + jl], bo = BiasS[96 + jl];

    float cst[2][2] = {{0.f, 0.f}, {0.f, 0.f}};
    uint32_t pf[2][2] = {{0, 0}, {0, 0}}, pd[2][2] = {{0, 0}, {0, 0}};

    for (int t = 0; t < SEQ; ++t) {
        const int p = t & 1;

        // prefetch x_{t+1}
        float4 xpre;
        const bool do_x = (tid < MG) && (t + 1 < SEQ);
        if (do_x)
            xpre = *(const float4*)(x + ((size_t)(bbase + tid) * SEQ + (t + 1)) * IND);

        #pragma unroll
        for (int gam = 0; gam < 2; ++gam) {
            const uint32_t mbfull_p = sbase + (gam * 2 + p) * 8;
            const uint32_t mbfull_n = sbase + (gam * 2 + (p ^ 1)) * 8;
            const uint32_t mbdone_p = sbase + 32 + (gam * 2 + p) * 8;
            const uint32_t mbdone_n = sbase + 32 + (gam * 2 + (p ^ 1)) * 8;

            // wait for this group's A buffer (t=0: locally zeroed)
            if (t > 0) {
                mbar_wait(mbfull_p, pf[gam][p]);
                pf[gam][p] ^= 1;
                if (tid == 0) mbar_expect(mbfull_p, FULL_TX);
            }

            // ---- z_partial(kg) = h @ W^T for this warp's 32 n-rows ----
            const uint32_t* Au = (const uint32_t*)(As + (gam * 2 + p) * AS_BUF);
            float acc[4][4];
            #pragma unroll
            for (int s = 0; s < 4; ++s)
                #pragma unroll
                for (int q = 0; q < 4; ++q) acc[s][q] = 0.0f;

            #pragma unroll
            for (int kt = 0; kt < 16; ++kt) {
                const int kb = kg * 128 + kt * 8 + tig;
                uint2 A0  = *(const uint2*)(Au + (size_t)kb * AS_KSTR + 2 * g);
                uint2 A0b = *(const uint2*)(Au + (size_t)(kb + 4) * AS_KSTR + 2 * g);
                #pragma unroll
                for (int s = 0; s < 4; ++s) {
                    asm("mma.sync.aligned.m16n8k8.row.col.f32.tf32.tf32.f32 "
                        "{%0,%1,%2,%3},{%4,%5,%6,%7},{%8,%9},{%0,%1,%2,%3};"
                        : "+f"(acc[s][0]), "+f"(acc[s][1]), "+f"(acc[s][2]), "+f"(acc[s][3])
                        : "r"(A0.x), "r"(A0.y), "r"(A0b.x), "r"(A0b.y),
                          "r"(Breg[s][kt][0]), "r"(Breg[s][kt][1]));
                }
            }
            {
                float* Zp = Zs + kg * ZS_BUF;
                #pragma unroll
                for (int s = 0; s < 4; ++s) {
                    const int n0 = nq * 32 + s * 8;
                    *(float2*)(Zp + (size_t)g * ZS_RSTR + n0 + 2 * tig) =
                        make_float2(acc[s][0], acc[s][1]);
                    *(float2*)(Zp + (size_t)(g + 8) * ZS_RSTR + n0 + 2 * tig) =
                        make_float2(acc[s][2], acc[s][3]);
                }
            }
            __syncthreads();

            // signal "A[gam][p] consumed" to all cluster CTAs (one arrive per thread)
            if (tid < CLUSTER) mbar_arrive_remote(mbdone_p, (uint32_t)tid);
            // stash prefetched x once per step (covered by later syncs)
            if (gam == 0 && do_x)
                *(float4*)(Xs + (p ^ 1) * (MG * 4) + tid * 4) = xpre;

            // ---- gates: rows {gam*16+qh, gam*16+qh+8}, column j0+jl ----
            float h0, h1;
            {
                const int r0 = gam * MGG + qh;
                const float4 xv0 = *(const float4*)(Xs + p * (MG * 4) + r0 * 4);
                const float4 xv1 = *(const float4*)(Xs + p * (MG * 4) + (r0 + 8) * 4);
                const float* z0 = Zs + (size_t)qh * ZS_RSTR;        // kg 0
                const float* z1 = z0 + ZS_BUF;                      // kg 1
                const float* y0 = Zs + (size_t)(qh + 8) * ZS_RSTR;
                const float* y1 = y0 + ZS_BUF;
                float ai = z0[jl]      + z1[jl]      + bi + dot4(wiv, xv0);
                float af = z0[32 + jl] + z1[32 + jl] + bf + dot4(wfv, xv0);
                float ag = z0[64 + jl] + z1[64 + jl] + bg + dot4(wgv, xv0);
                float ao = z0[96 + jl] + z1[96 + jl] + bo + dot4(wov, xv0);
                float gi = sig_t(ai), gf = sig_t(af), go = sig_t(ao);
                float gg = tanh_a(ag);
                float cn = gf * cst[gam][0] + gi * gg;
                cst[gam][0] = cn;
                h0 = rtf32(go * tanh_a(cn));

                ai = y0[jl]      + y1[jl]      + bi + dot4(wiv, xv1);
                af = y0[32 + jl] + y1[32 + jl] + bf + dot4(wfv, xv1);
                ag = y0[64 + jl] + y1[64 + jl] + bg + dot4(wgv, xv1);
                ao = y0[96 + jl] + y1[96 + jl] + bo + dot4(wov, xv1);
                gi = sig_t(ai); gf = sig_t(af); go = sig_t(ao);
                gg = tanh_a(ag);
                cn = gf * cst[gam][1] + gi * gg;
                cst[gam][1] = cn;
                h1 = rtf32(go * tanh_a(cn));
            }
            // publish own slice to L2 staging (interleaved A layout, stride 20)
            __stcg((float2*)&g_hx[cid][gam][p ^ 1]
                       [(size_t)rank * SLICE_W + jl * AS_KSTR + 2 * qh],
                   make_float2(h0, h1));
            __syncthreads();   // all slice STGs issued before elected fence

            // elected: wait peers consumed A[gam][p^1], then ONE multicast bulk
            if (tid == 0) {
                if (t > 0) { mbar_wait(mbdone_n, pd[gam][p ^ 1]); pd[gam][p ^ 1] ^= 1; }
                asm volatile("fence.proxy.async.global;" ::: "memory");
                const uint32_t dstl =
                    sbase + (OFF_AS + (gam * 2 + (p ^ 1)) * AS_BUF + j0 * AS_KSTR) * 4;
                bulk_mc_g2s(dstl, &g_hx[cid][gam][p ^ 1][(size_t)rank * SLICE_W],
                            SLICE_B, mbfull_n, (uint16_t)0xFF);
            }

            if (t == SEQ - 1) {
                const int r0 = gam * MGG + qh;
                g_hfin[(size_t)(bbase + r0) * HID + j0 + jl]     = h0;
                g_hfin[(size_t)(bbase + r0 + 8) * HID + j0 + jl] = h1;
            }
        }
    }

    // drain final incoming multicasts (t=2047 targeted full[g][0]) before exit
    mbar_wait(sbase + 0 * 8, pf[0][0]);   // full[0][0]
    mbar_wait(sbase + 2 * 8, pf[1][0]);   // full[1][0]
    asm volatile("barrier.cluster.arrive.aligned;" ::: "memory");
    asm volatile("barrier.cluster.wait.aligned;"   ::: "memory");
}

// ---------------------------------------------------------------------------
// Kernel 3: head
// ---------------------------------------------------------------------------
__global__ void head_kernel(const float* __restrict__ fc_w,
                            const float* __restrict__ fc_b,
                            const float* __restrict__ out_w,
                            const float* __restrict__ out_b,
                            float* __restrict__ out) {
    __shared__ float hsh[HID];
    __shared__ float r0[256];
    __shared__ float r1[256];
    int b = blockIdx.x, tid = threadIdx.x;
    hsh[tid] = g_hfin[b * HID + tid];
    __syncthreads();
    float cf = g_feat[b], ks = g_feat[BATCH + b];
    const float* wr = fc_w + (size_t)tid * (HID + 2);
    float acc = fc_b[tid] + wr[0] * cf + wr[HID + 1] * ks;
    #pragma unroll 8
    for (int k = 0; k < HID; ++k) acc += wr[1 + k] * hsh[k];
    float hid = fmaxf(acc, 0.0f);
    r0[tid] = hid * out_w[tid];
    r1[tid] = hid * out_w[HID + tid];
    __syncthreads();
    for (int o = 128; o > 0; o >>= 1) {
        if (tid < o) { r0[tid] += r0[tid + o]; r1[tid] += r1[tid + o]; }
        __syncthreads();
    }
    if (tid == 0) {
        float l0 = r0[0] + out_b[0];
        float l1 = r1[0] + out_b[1];
        float m  = fmaxf(l0, l1);
        float e0 = __expf(l0 - m), e1 = __expf(l1 - m);
        float inv = __fdividef(1.0f, e0 + e1);
        out[b * 2 + 0] = e0 * inv;
        out[b * 2 + 1] = e1 * inv;
    }
}

// ---------------------------------------------------------------------------
// launch (lstm first so the fixed ncu sampling slot captures it)
// ---------------------------------------------------------------------------
extern "C" void kernel_launch(void* const* d_in, const int* in_sizes, int n_in,
                              void* d_out, int out_size) {
    const float* x      = (const float*)d_in[0];
    const float* conv_w = (const float*)d_in[1];
    const float* conv_b = (const float*)d_in[2];
    const float* W_ih   = (const float*)d_in[3];
    const float* W_hh   = (const float*)d_in[4];
    const float* b_ih   = (const float*)d_in[5];
    const float* b_hh   = (const float*)d_in[6];
    const float* fc_w   = (const float*)d_in[7];
    const float* fc_b   = (const float*)d_in[8];
    const float* out_w  = (const float*)d_in[9];
    const float* out_b  = (const float*)d_in[10];
    float* out = (float*)d_out;

    cudaFuncSetAttribute(lstm_kernel, cudaFuncAttributeMaxDynamicSharedMemorySize,
                         SMEM_BYTES);

    lstm_kernel<<<NCLUST * CLUSTER, THREADS, SMEM_BYTES>>>(x, W_ih, W_hh, b_ih, b_hh);
    feat_kernel<<<BATCH, 256>>>(x, conv_w, conv_b);
    head_kernel<<<BATCH, 256>>>(fc_w, fc_b, out_w, out_b, out);
}

// round 10
// speedup vs baseline: 2.1327x; 1.0386x over previous
#include <cuda_runtime.h>
#include <cstdint>

// ---------------------------------------------------------------------------
// Problem constants
// ---------------------------------------------------------------------------
#define BATCH  256
#define SEQ    2048
#define IND    4
#define HID    256

// 8 clusters x 8 CTAs = 64 CTAs (single wave).
// Cluster owns 32 batch rows, split into TWO independent pipelined groups of
// 16 rows. CTA rank r owns h-indices [32r,32r+32) -> 128 W_hh rows as tf32
// register fragments. 8 warps: warp = (kg in {0,1}, nq in {0..3}).
// Exchange: STG slice -> L2, ONE cp.async.bulk multicast::cluster per CTA per
// group delivers into all 8 CTAs' A buffers. A is TRIPLE-buffered per group:
// the full-barrier chain transitively guarantees the target phase is free,
// so there is NO consume/done barrier at all.
#define CLUSTER 8
#define NCLUST  8
#define MG      32
#define MGG     16      // rows per pipeline group
#define JPC     32
#define THREADS 256

#define AS_KSTR 20                      // 16 rows + 4 pad words
#define AS_BUF  (HID * AS_KSTR)         // 5120 floats per buffer
#define ZS_RSTR 132
#define ZS_BUF  (MGG * ZS_RSTR)         // 2112 floats per k-group
#define SLICE_W (JPC * AS_KSTR)         // 640 words per CTA slice
#define SLICE_B (SLICE_W * 4)           // 2560 bytes
#define FULL_TX (8 * SLICE_B)           // 20480 bytes (8 multicast slices)

// dynamic smem layout (float offsets)
// mbarriers: full[g][ph] at (g*3+ph)*8 bytes (6 barriers, 48 B)
#define OFF_AS    16
#define OFF_ZS    (OFF_AS + 6 * AS_BUF)      // 30736 (A[g][ph] = (g*3+ph)*AS_BUF)
#define OFF_WIH   (OFF_ZS + 2 * ZS_BUF)      // 34960
#define OFF_BIAS  (OFF_WIH + 512)            // 35472
#define OFF_XS    (OFF_BIAS + 128)           // 35600
#define SMEM_FLOATS (OFF_XS + 2 * MG * 4)    // 35856
#define SMEM_BYTES  (SMEM_FLOATS * 4)        // 143424

// ---------------------------------------------------------------------------
// Global scratch
// ---------------------------------------------------------------------------
__device__ float g_hx[NCLUST][2][3][CLUSTER * SLICE_W];  // [clust][group][phase]
__device__ float g_hfin[BATCH * HID];
__device__ float g_feat[2 * BATCH];

// ---------------------------------------------------------------------------
// helpers
// ---------------------------------------------------------------------------
__device__ __forceinline__ uint32_t tf32u(float v) {
    uint32_t r; asm("cvt.rna.tf32.f32 %0, %1;" : "=r"(r) : "f"(v)); return r;
}
__device__ __forceinline__ float rtf32(float v) { return __uint_as_float(tf32u(v)); }
__device__ __forceinline__ float tanh_a(float x) {
    float y; asm("tanh.approx.f32 %0, %1;" : "=f"(y) : "f"(x)); return y;
}
__device__ __forceinline__ float sig_t(float x) { return 0.5f * tanh_a(0.5f * x) + 0.5f; }
__device__ __forceinline__ float fast_sigmoid(float x) {
    float e = __expf(-x); return __fdividef(1.0f, 1.0f + e);
}
__device__ __forceinline__ float dot4(float4 a, float4 b) {
    return a.x * b.x + a.y * b.y + a.z * b.z + a.w * b.w;
}
__device__ __forceinline__ uint32_t smem_u32(const void* p) {
    uint32_t a;
    asm("{ .reg .u64 t; cvta.to.shared.u64 t, %1; cvt.u32.u64 %0, t; }" : "=r"(a) : "l"(p));
    return a;
}
__device__ __forceinline__ uint32_t cta_rank() {
    uint32_t r; asm("mov.u32 %0, %%cluster_ctarank;" : "=r"(r)); return r;
}
__device__ __forceinline__ void mbar_init(uint32_t mbar, uint32_t cnt) {
    asm volatile("mbarrier.init.shared.b64 [%0], %1;" :: "r"(mbar), "r"(cnt) : "memory");
}
__device__ __forceinline__ void mbar_expect(uint32_t mbar, uint32_t bytes) {
    asm volatile("mbarrier.arrive.expect_tx.shared.b64 _, [%0], %1;"
                 :: "r"(mbar), "r"(bytes) : "memory");
}
__device__ __forceinline__ void mbar_wait(uint32_t mbar, uint32_t parity) {
    asm volatile(
        "{\n\t.reg .pred P;\n\t"
        "W_%=:\n\t"
        "mbarrier.try_wait.parity.acquire.cta.shared::cta.b64 P, [%0], %1, 0x989680;\n\t"
        "@P bra D_%=;\n\t"
        "bra W_%=;\n\t"
        "D_%=:\n\t}"
        :: "r"(mbar), "r"(parity) : "memory");
}
// one bulk, delivered to every CTA in ctaMask at the same local dst offset
__device__ __forceinline__ void bulk_mc_g2s(uint32_t dst, const void* src,
                                            uint32_t bytes, uint32_t mbar,
                                            uint16_t mask) {
    asm volatile("cp.async.bulk.shared::cluster.global."
                 "mbarrier::complete_tx::bytes.multicast::cluster "
                 "[%0], [%1], %2, [%3], %4;"
                 :: "r"(dst), "l"(src), "r"(bytes), "r"(mbar), "h"(mask) : "memory");
}

// ---------------------------------------------------------------------------
// Kernel 1: conv_feat + kernel_sim
// ---------------------------------------------------------------------------
__global__ void feat_kernel(const float* __restrict__ x,
                            const float* __restrict__ conv_w,
                            const float* __restrict__ conv_b) {
    __shared__ float r0[256];
    __shared__ float r1[256];
    int b = blockIdx.x, tid = threadIdx.x;
    float4 cw = *(const float4*)conv_w;
    float cb = conv_b[0];
    const float4* xr = (const float4*)(x + (size_t)b * SEQ * IND);
    float ssig = 0.f, ssq = 0.f;
    for (int s = tid; s < SEQ; s += 256) {
        float4 v = xr[s];
        float d = v.x * cw.x + v.y * cw.y + v.z * cw.z + v.w * cw.w + cb;
        ssig += fast_sigmoid(d);
        ssq  += v.x * v.x + v.y * v.y + v.z * v.z + v.w * v.w;
    }
    r0[tid] = ssig; r1[tid] = ssq;
    __syncthreads();
    for (int o = 128; o > 0; o >>= 1) {
        if (tid < o) { r0[tid] += r0[tid + o]; r1[tid] += r1[tid + o]; }
        __syncthreads();
    }
    if (tid == 0) {
        g_feat[b]         = r0[0] * (1.0f / SEQ);
        g_feat[BATCH + b] = __expf(-r1[0]);
    }
}

// ---------------------------------------------------------------------------
// Kernel 2: LSTM recurrence; two pipelined groups, triple-buffered A,
// no consume barrier.
// ---------------------------------------------------------------------------
__global__ void __cluster_dims__(CLUSTER, 1, 1) __launch_bounds__(THREADS, 1)
lstm_kernel(const float* __restrict__ x,
            const float* __restrict__ W_ih,
            const float* __restrict__ W_hh,
            const float* __restrict__ b_ih,
            const float* __restrict__ b_hh) {
    extern __shared__ float sm[];
    float* As    = sm + OFF_AS;
    float* Zs    = sm + OFF_ZS;
    float* WihS  = sm + OFF_WIH;
    float* BiasS = sm + OFF_BIAS;
    float* Xs    = sm + OFF_XS;

    const uint32_t sbase = smem_u32(sm);

    const int tid   = threadIdx.x;
    const int cid   = blockIdx.x / CLUSTER;
    const uint32_t rank = cta_rank();
    const int bbase = cid * MG;
    const int j0    = (int)rank * JPC;
    const int warp  = tid >> 5, lane = tid & 31;
    const int kg    = warp >> 2, nq = warp & 3;
    const int g     = lane >> 2, tig = lane & 3;

    // ---- one-time: W_hh register fragments (tf32) ----
    uint32_t Breg[4][16][2];
    #pragma unroll
    for (int s = 0; s < 4; ++s) {
        const int nl   = nq * 32 + s * 8 + g;
        const int gate = nl >> 5, jj = nl & 31;
        const float* wrow = W_hh + (size_t)(gate * HID + j0 + jj) * HID + kg * 128;
        #pragma unroll
        for (int kt = 0; kt < 16; ++kt) {
            Breg[s][kt][0] = tf32u(wrow[kt * 8 + tig]);
            Breg[s][kt][1] = tf32u(wrow[kt * 8 + tig + 4]);
        }
    }
    if (tid < 128) {
        int gate = tid >> 5, jj = tid & 31;
        int grow = gate * HID + j0 + jj;
        BiasS[tid] = b_ih[grow] + b_hh[grow];
        WihS[tid * 4 + 0] = W_ih[grow * IND + 0];
        WihS[tid * 4 + 1] = W_ih[grow * IND + 1];
        WihS[tid * 4 + 2] = W_ih[grow * IND + 2];
        WihS[tid * 4 + 3] = W_ih[grow * IND + 3];
    }
    // zero phase-0 A buffers of both groups (h_0 = 0)
    for (int i = tid; i < AS_BUF; i += THREADS) {
        As[i] = 0.0f;                 // group 0, phase 0
        As[3 * AS_BUF + i] = 0.0f;    // group 1, phase 0
    }
    if (tid < MG)
        *(float4*)(Xs + tid * 4) = *(const float4*)(x + (size_t)(bbase + tid) * SEQ * IND);
    if (tid == 0) {
        #pragma unroll
        for (int i = 0; i < 6; ++i) {
            mbar_init(sbase + i * 8, 1);        // full[g][ph]
            mbar_expect(sbase + i * 8, FULL_TX);
        }
        asm volatile("fence.mbarrier_init.release.cluster;" ::: "memory");
    }
    __syncthreads();
    asm volatile("barrier.cluster.arrive.aligned;" ::: "memory");
    asm volatile("barrier.cluster.wait.aligned;"   ::: "memory");

    // gate-phase ownership: col jl = tid&31; thread qh = tid>>5 owns group rows
    // {qh, qh+8}  (interleave positions 2qh, 2qh+1)
    const int jl = tid & 31;
    const int qh = tid >> 5;

    // hoisted loop-invariant gate weights/biases
    const float4 wiv = *(const float4*)(WihS + (jl)      * 4);
    const float4 wfv = *(const float4*)(WihS + (32 + jl) * 4);
    const float4 wgv = *(const float4*)(WihS + (64 + jl) * 4);
    const float4 wov = *(const float4*)(WihS + (96 + jl) * 4);
    const float bi = BiasS[jl], bf = BiasS[32 + jl];
    const float bg = BiasS[64 + jl], bo = BiasS[96 + jl];

    float cst[2][2] = {{0.f, 0.f}, {0.f, 0.f}};
    uint32_t pf[2][3] = {{0, 0, 0}, {0, 0, 0}};

    int ph = 0;   // t % 3
    for (int t = 0; t < SEQ; ++t) {
        const int p   = t & 1;               // Xs parity only
        const int ph1 = (ph == 2) ? 0 : ph + 1;

        // prefetch x_{t+1}
        float4 xpre;
        const bool do_x = (tid < MG) && (t + 1 < SEQ);
        if (do_x)
            xpre = *(const float4*)(x + ((size_t)(bbase + tid) * SEQ + (t + 1)) * IND);

        #pragma unroll
        for (int gam = 0; gam < 2; ++gam) {
            const uint32_t mbfull_p = sbase + (gam * 3 + ph) * 8;
            const uint32_t mbfull_n = sbase + (gam * 3 + ph1) * 8;

            // wait for this group's A phase (t=0: locally zeroed)
            if (t > 0) {
                mbar_wait(mbfull_p, pf[gam][ph]);
                pf[gam][ph] ^= 1;
                if (tid == 0) mbar_expect(mbfull_p, FULL_TX);
            }

            // ---- z_partial(kg) = h @ W^T for this warp's 32 n-rows ----
            const uint32_t* Au = (const uint32_t*)(As + (gam * 3 + ph) * AS_BUF);
            float acc[4][4];
            #pragma unroll
            for (int s = 0; s < 4; ++s)
                #pragma unroll
                for (int q = 0; q < 4; ++q) acc[s][q] = 0.0f;

            #pragma unroll
            for (int kt = 0; kt < 16; ++kt) {
                const int kb = kg * 128 + kt * 8 + tig;
                uint2 A0  = *(const uint2*)(Au + (size_t)kb * AS_KSTR + 2 * g);
                uint2 A0b = *(const uint2*)(Au + (size_t)(kb + 4) * AS_KSTR + 2 * g);
                #pragma unroll
                for (int s = 0; s < 4; ++s) {
                    asm("mma.sync.aligned.m16n8k8.row.col.f32.tf32.tf32.f32 "
                        "{%0,%1,%2,%3},{%4,%5,%6,%7},{%8,%9},{%0,%1,%2,%3};"
                        : "+f"(acc[s][0]), "+f"(acc[s][1]), "+f"(acc[s][2]), "+f"(acc[s][3])
                        : "r"(A0.x), "r"(A0.y), "r"(A0b.x), "r"(A0b.y),
                          "r"(Breg[s][kt][0]), "r"(Breg[s][kt][1]));
                }
            }
            {
                float* Zp = Zs + kg * ZS_BUF;
                #pragma unroll
                for (int s = 0; s < 4; ++s) {
                    const int n0 = nq * 32 + s * 8;
                    *(float2*)(Zp + (size_t)g * ZS_RSTR + n0 + 2 * tig) =
                        make_float2(acc[s][0], acc[s][1]);
                    *(float2*)(Zp + (size_t)(g + 8) * ZS_RSTR + n0 + 2 * tig) =
                        make_float2(acc[s][2], acc[s][3]);
                }
            }
            __syncthreads();

            // stash prefetched x once per step (covered by later syncs)
            if (gam == 0 && do_x)
                *(float4*)(Xs + (p ^ 1) * (MG * 4) + tid * 4) = xpre;

            // ---- gates: rows {gam*16+qh, gam*16+qh+8}, column j0+jl ----
            float h0, h1;
            {
                const int r0 = gam * MGG + qh;
                const float4 xv0 = *(const float4*)(Xs + p * (MG * 4) + r0 * 4);
                const float4 xv1 = *(const float4*)(Xs + p * (MG * 4) + (r0 + 8) * 4);
                const float* z0 = Zs + (size_t)qh * ZS_RSTR;        // kg 0
                const float* z1 = z0 + ZS_BUF;                      // kg 1
                const float* y0 = Zs + (size_t)(qh + 8) * ZS_RSTR;
                const float* y1 = y0 + ZS_BUF;
                float ai = z0[jl]      + z1[jl]      + bi + dot4(wiv, xv0);
                float af = z0[32 + jl] + z1[32 + jl] + bf + dot4(wfv, xv0);
                float ag = z0[64 + jl] + z1[64 + jl] + bg + dot4(wgv, xv0);
                float ao = z0[96 + jl] + z1[96 + jl] + bo + dot4(wov, xv0);
                float gi = sig_t(ai), gf = sig_t(af), go = sig_t(ao);
                float gg = tanh_a(ag);
                float cn = gf * cst[gam][0] + gi * gg;
                cst[gam][0] = cn;
                h0 = rtf32(go * tanh_a(cn));

                ai = y0[jl]      + y1[jl]      + bi + dot4(wiv, xv1);
                af = y0[32 + jl] + y1[32 + jl] + bf + dot4(wfv, xv1);
                ag = y0[64 + jl] + y1[64 + jl] + bg + dot4(wgv, xv1);
                ao = y0[96 + jl] + y1[96 + jl] + bo + dot4(wov, xv1);
                gi = sig_t(ai); gf = sig_t(af); go = sig_t(ao);
                gg = tanh_a(ag);
                cn = gf * cst[gam][1] + gi * gg;
                cst[gam][1] = cn;
                h1 = rtf32(go * tanh_a(cn));
            }

            if (t + 1 < SEQ) {
                // publish own slice to L2 staging (interleaved A layout, stride 20)
                __stcg((float2*)&g_hx[cid][gam][ph1]
                           [(size_t)rank * SLICE_W + jl * AS_KSTR + 2 * qh],
                       make_float2(h0, h1));
                __syncthreads();   // all slice STGs issued before elected fence

                // elected: ONE multicast bulk to all 8 CTAs' A[gam][ph1].
                // No consume barrier needed: passing full[gam][ph] above
                // transitively proves every peer finished reading ph1 (t-2).
                if (tid == 0) {
                    asm volatile("fence.proxy.async.global;" ::: "memory");
                    const uint32_t dstl =
                        sbase + (OFF_AS + (gam * 3 + ph1) * AS_BUF + j0 * AS_KSTR) * 4;
                    bulk_mc_g2s(dstl, &g_hx[cid][gam][ph1][(size_t)rank * SLICE_W],
                                SLICE_B, mbfull_n, (uint16_t)0xFF);
                }
            } else {
                g_hfin[(size_t)(bbase + gam * MGG + qh) * HID + j0 + jl]     = h0;
                g_hfin[(size_t)(bbase + gam * MGG + qh + 8) * HID + j0 + jl] = h1;
            }
        }
        ph = ph1;
    }

    // no publish was issued at t=SEQ-1, so nothing in flight toward us beyond
    // the full[ph(SEQ-1)] we already consumed.
    asm volatile("barrier.cluster.arrive.aligned;" ::: "memory");
    asm volatile("barrier.cluster.wait.aligned;"   ::: "memory");
}

// ---------------------------------------------------------------------------
// Kernel 3: head
// ---------------------------------------------------------------------------
__global__ void head_kernel(const float* __restrict__ fc_w,
                            const float* __restrict__ fc_b,
                            const float* __restrict__ out_w,
                            const float* __restrict__ out_b,
                            float* __restrict__ out) {
    __shared__ float hsh[HID];
    __shared__ float r0[256];
    __shared__ float r1[256];
    int b = blockIdx.x, tid = threadIdx.x;
    hsh[tid] = g_hfin[b * HID + tid];
    __syncthreads();
    float cf = g_feat[b], ks = g_feat[BATCH + b];
    const float* wr = fc_w + (size_t)tid * (HID + 2);
    float acc = fc_b[tid] + wr[0] * cf + wr[HID + 1] * ks;
    #pragma unroll 8
    for (int k = 0; k < HID; ++k) acc += wr[1 + k] * hsh[k];
    float hid = fmaxf(acc, 0.0f);
    r0[tid] = hid * out_w[tid];
    r1[tid] = hid * out_w[HID + tid];
    __syncthreads();
    for (int o = 128; o > 0; o >>= 1) {
        if (tid < o) { r0[tid] += r0[tid + o]; r1[tid] += r1[tid + o]; }
        __syncthreads();
    }
    if (tid == 0) {
        float l0 = r0[0] + out_b[0];
        float l1 = r1[0] + out_b[1];
        float m  = fmaxf(l0, l1);
        float e0 = __expf(l0 - m), e1 = __expf(l1 - m);
        float inv = __fdividef(1.0f, e0 + e1);
        out[b * 2 + 0] = e0 * inv;
        out[b * 2 + 1] = e1 * inv;
    }
}

// ---------------------------------------------------------------------------
// launch (lstm first so the fixed ncu sampling slot captures it)
// ---------------------------------------------------------------------------
extern "C" void kernel_launch(void* const* d_in, const int* in_sizes, int n_in,
                              void* d_out, int out_size) {
    const float* x      = (const float*)d_in[0];
    const float* conv_w = (const float*)d_in[1];
    const float* conv_b = (const float*)d_in[2];
    const float* W_ih   = (const float*)d_in[3];
    const float* W_hh   = (const float*)d_in[4];
    const float* b_ih   = (const float*)d_in[5];
    const float* b_hh   = (const float*)d_in[6];
    const float* fc_w   = (const float*)d_in[7];
    const float* fc_b   = (const float*)d_in[8];
    const float* out_w  = (const float*)d_in[9];
    const float* out_b  = (const float*)d_in[10];
    float* out = (float*)d_out;

    cudaFuncSetAttribute(lstm_kernel, cudaFuncAttributeMaxDynamicSharedMemorySize,
                         SMEM_BYTES);

    lstm_kernel<<<NCLUST * CLUSTER, THREADS, SMEM_BYTES>>>(x, W_ih, W_hh, b_ih, b_hh);
    feat_kernel<<<BATCH, 256>>>(x, conv_w, conv_b);
    head_kernel<<<BATCH, 256>>>(fc_w, fc_b, out_w, out_b, out);
}